// round 16
// baseline (speedup 1.0000x reference)
#include <cuda_runtime.h>
#include <cuda_fp16.h>
#include <math.h>
#include <stdint.h>

#define TPB   128
#define GRID  444            // 148 SMs * 3 CTAs
#define NNK   131072         // N*K per (b,c) plane
#define NWT   32768          // total warp tiles (1,048,576 pos / 32)
#define DPITCH 66            // floats per ddt row (kk-stride 4 -> distinct banks)

// ---- smem layout (bytes) ----
// packed weight quads: row pitch 160B, 64 rows = 10240B each
#define OFF_P1   0           // cf_w2
#define OFF_P2   10240       // pl_w2
#define OFF_P3   20480       // folded ge_w1
#define OFF_P4   30720       // ge_w2
#define OFF_P56  40960       // stage0: [W5 pair | W6 pair] per (row,T)
#define OFF_b1v  51200       // cf_b2 f32
#define OFF_b2v  51456       // pl_b2
#define OFF_b3v  51712       // folded ge bias
#define OFF_bov  51968       // ge_b2
#define OFF_DDT  52224       // d transposed [16][DPITCH] f32
#define SMEM_BYTES (OFF_DDT + 16*DPITCH*4)   // 56448 -> 3 CTAs/SM

__device__ __forceinline__ void mma16816(float* c, const uint32_t* a,
                                         uint32_t b0, uint32_t b1) {
    asm volatile(
        "mma.sync.aligned.m16n8k16.row.col.f32.f16.f16.f32 "
        "{%0,%1,%2,%3}, {%4,%5,%6,%7}, {%8,%9}, {%0,%1,%2,%3};"
        : "+f"(c[0]), "+f"(c[1]), "+f"(c[2]), "+f"(c[3])
        : "r"(a[0]), "r"(a[1]), "r"(a[2]), "r"(a[3]), "r"(b0), "r"(b1));
}
__device__ __forceinline__ void mma16808(float* c, uint32_t a0, uint32_t a1,
                                         uint32_t b0) {
    asm volatile(
        "mma.sync.aligned.m16n8k8.row.col.f32.f16.f16.f32 "
        "{%0,%1,%2,%3}, {%4,%5}, {%6}, {%0,%1,%2,%3};"
        : "+f"(c[0]), "+f"(c[1]), "+f"(c[2]), "+f"(c[3])
        : "r"(a0), "r"(a1), "r"(b0));
}
__device__ __forceinline__ uint32_t pack2(float a, float b) {
    __half2 h = __floats2half2_rn(a, b);
    return *reinterpret_cast<uint32_t*>(&h);
}

__global__ void __launch_bounds__(TPB, 3) geo_hmma_kernel(
    const float* __restrict__ nb,    const float* __restrict__ cx,    const float* __restrict__ dmat,
    const float* __restrict__ cf_w1, const float* __restrict__ cf_b1, const float* __restrict__ cf_g,
    const float* __restrict__ cf_be, const float* __restrict__ cf_m,  const float* __restrict__ cf_v,
    const float* __restrict__ cf_w2, const float* __restrict__ cf_b2,
    const float* __restrict__ pl_w1, const float* __restrict__ pl_b1, const float* __restrict__ pl_g,
    const float* __restrict__ pl_be, const float* __restrict__ pl_m,  const float* __restrict__ pl_v,
    const float* __restrict__ pl_w2, const float* __restrict__ pl_b2,
    const float* __restrict__ ge_w1, const float* __restrict__ ge_b1, const float* __restrict__ ge_g,
    const float* __restrict__ ge_be, const float* __restrict__ ge_m,  const float* __restrict__ ge_v,
    const float* __restrict__ ge_w2, const float* __restrict__ ge_b2,
    float* __restrict__ out)
{
    extern __shared__ char smc[];
    __half* P1  = (__half*)(smc + OFF_P1);
    __half* P2  = (__half*)(smc + OFF_P2);
    __half* P3  = (__half*)(smc + OFF_P3);
    __half* P4  = (__half*)(smc + OFF_P4);
    __half* P56 = (__half*)(smc + OFF_P56);
    float*  b1v = (float*)(smc + OFF_b1v);
    float*  b2v = (float*)(smc + OFF_b2v);
    float*  b3v = (float*)(smc + OFF_b3v);
    float*  bov = (float*)(smc + OFF_bov);
    float*  DDT = (float*)(smc + OFF_DDT);

    const int tid = threadIdx.x;

    // ---- prologue: fold BN, convert to f16, pack B-fragment quads ----
    // quad layout (halfs): doff = row*80 + t*16 + T*4 + slot
    //   slot 0,1 = k 16t+2T, 16t+2T+1  (b0) ; slot 2,3 = k 16t+2T+8, +9 (b1)
    for (int idx = tid; idx < 4096; idx += TPB) {
        int n_ = idx >> 6, k_ = idx & 63;
        int t  = k_ >> 4, r_ = k_ & 15;
        int hi = r_ >> 3;
        int Tq = (r_ & 7) >> 1;
        int slot = hi * 2 + (r_ & 1);
        int doff = n_ * 80 + t * 16 + Tq * 4 + slot;
        float s3 = ge_g[n_] * rsqrtf(ge_v[n_] + 1e-5f);
        P1[doff] = __float2half_rn(cf_w2[idx]);
        P2[doff] = __float2half_rn(pl_w2[idx]);
        P3[doff] = __float2half_rn(s3 * ge_w1[idx]);
        P4[doff] = __float2half_rn(ge_w2[idx]);
    }
    for (int idx = tid; idx < 1024; idx += TPB) {
        int c_ = idx >> 4, k_ = idx & 15;
        DDT[k_ * DPITCH + c_] = dmat[idx];
    }
    if (tid < 64) {
        const int c = tid;
        float s  = cf_g[c] * rsqrtf(cf_v[c] + 1e-5f);
        float s2 = pl_g[c] * rsqrtf(pl_v[c] + 1e-5f);
        float w5[8], w6[8];
#pragma unroll
        for (int i = 0; i < 8; ++i) { w5[i] = 0.f; w6[i] = 0.f; }
        w5[0] = s * cf_w1[c*4+0];  w5[1] = s * cf_w1[c*4+1];
        w5[2] = s * cf_w1[c*4+2];  w5[3] = s * cf_w1[c*4+3];
        w5[6] = s * (cf_b1[c] - cf_m[c]) + cf_be[c];
        w6[4] = s2 * pl_w1[c*2+0]; w6[5] = s2 * pl_w1[c*2+1];
        w6[6] = s2 * (pl_b1[c] - pl_m[c]) + pl_be[c];
#pragma unroll
        for (int T = 0; T < 4; ++T) {
            int base = c * 80 + T * 4;
            P56[base+0] = __float2half_rn(w5[2*T]);
            P56[base+1] = __float2half_rn(w5[2*T+1]);
            P56[base+2] = __float2half_rn(w6[2*T]);
            P56[base+3] = __float2half_rn(w6[2*T+1]);
        }
        float s3 = ge_g[c] * rsqrtf(ge_v[c] + 1e-5f);
        b3v[c] = s3 * (ge_b1[c] - ge_m[c]) + ge_be[c];
        b1v[c] = cf_b2[c];
        b2v[c] = pl_b2[c];
        bov[c] = ge_b2[c];
    }
    __syncthreads();

    const int lane = tid & 31;
    const int g    = lane >> 2;        // 0..7
    const int T    = lane & 3;         // 0..3
    const int warp_global = blockIdx.x * (TPB/32) + (tid >> 5);
    const int stride = GRID * (TPB/32);

    const uint32_t PCONST = pack2(1.f, 0.f);   // X cols 6,7

    // Position permutation: MMA row (16m+8h+g) holds position (4g+2m+h).
    // Input gather src lane for (m,h) = 4g + 2m + h; store per channel is a
    // dense float4 at offset 4g.

    // ---- geometry prefetch for first tile ----
    float pnx, pny, pnz, pcx, pcy, pcz;
    {
        const int wt0 = warp_global;
        const int b   = wt0 >> 12;
        const int pgb = ((wt0 & 4095) << 5) + lane;
        const int n   = pgb >> 4;
        const float* nbb = nb + (size_t)b * 3 * NNK;
        const float* cxb = cx + (size_t)b * 3 * 8192;
        pnx = nbb[0*NNK + pgb];  pny = nbb[1*NNK + pgb];  pnz = nbb[2*NNK + pgb];
        pcx = cxb[0*8192 + n];   pcy = cxb[1*8192 + n];   pcz = cxb[2*8192 + n];
    }

    for (int wt = warp_global; wt < NWT; wt += stride) {
        const int b    = wt >> 12;               // 4096 tiles per batch
        const int pgb0 = (wt & 4095) << 5;       // base position in batch

        // ---- consume prefetched geometry (lane holds position pgb0+lane) ----
        const float dx = pnx - pcx;
        const float dy = pny - pcy;
        const float dz = pnz - pcz;
        const float r   = sqrtf(dx*dx + dy*dy + dz*dz);
        const float rxy = sqrtf(dx*dx + dy*dy);
        const float ce  = (r   > 0.f) ? (rxy / r)  : 0.f;
        const float ca  = (rxy > 0.f) ? (dy / rxy) : 0.f;

        // ---- issue next tile's loads; latency hides under the GEMM chain ----
        const int nwt = wt + stride;
        if (nwt < NWT) {
            const int nb_ = nwt >> 12;
            const int pgb = ((nwt & 4095) << 5) + lane;
            const int n   = pgb >> 4;
            const float* nbb = nb + (size_t)nb_ * 3 * NNK;
            const float* cxb = cx + (size_t)nb_ * 3 * 8192;
            pnx = nbb[0*NNK + pgb];  pny = nbb[1*NNK + pgb];  pnz = nbb[2*NNK + pgb];
            pcx = cxb[0*8192 + n];   pcy = cxb[1*8192 + n];   pcz = cxb[2*8192 + n];
        }

        // ---- build X A-fragments with permuted row<->position map ----
        const uint32_t p0 = pack2(dx, dy);
        const uint32_t p1 = pack2(dz, r);
        const uint32_t p2 = pack2(ca, ce);
        uint32_t xa[2][2];
#pragma unroll
        for (int rr = 0; rr < 4; ++rr) {           // rr = 2m + h
            const int src = 4*g + rr;              // lane holding position 4g+2m+h
            uint32_t q0 = __shfl_sync(0xffffffffu, p0, src);
            uint32_t q1 = __shfl_sync(0xffffffffu, p1, src);
            uint32_t q2 = __shfl_sync(0xffffffffu, p2, src);
            uint32_t v  = (T == 0) ? q0 : (T == 1) ? q1 : (T == 2) ? q2 : PCONST;
            xa[rr>>1][rr&1] = v;                   // xa[m][h]
        }

        // ---- stage 0: h1 = relu(X@W5^T), h2 = relu(X@W6^T) via k8 MMA ----
        uint32_t fa[2][4][4];
        uint32_t fb[2][4][4];
#pragma unroll
        for (int j = 0; j < 8; ++j) {
            const uint2 v56 = *(const uint2*)(smc + OFF_P56 + (8*j + g)*160 + T*8);
            float c5[2][4] = {{0,0,0,0},{0,0,0,0}};
            float c6[2][4] = {{0,0,0,0},{0,0,0,0}};
#pragma unroll
            for (int m = 0; m < 2; ++m) {
                mma16808(c5[m], xa[m][0], xa[m][1], v56.x);
                mma16808(c6[m], xa[m][0], xa[m][1], v56.y);
            }
#pragma unroll
            for (int m = 0; m < 2; ++m) {
                fa[m][j>>1][2*(j&1)+0] = pack2(fmaxf(c5[m][0],0.f), fmaxf(c5[m][1],0.f));
                fa[m][j>>1][2*(j&1)+1] = pack2(fmaxf(c5[m][2],0.f), fmaxf(c5[m][3],0.f));
                fb[m][j>>1][2*(j&1)+0] = pack2(fmaxf(c6[m][0],0.f), fmaxf(c6[m][1],0.f));
                fb[m][j>>1][2*(j&1)+1] = pack2(fmaxf(c6[m][2],0.f), fmaxf(c6[m][3],0.f));
            }
        }

        // ---- GEMM1 (h1 @ cf_w2^T) + GEMM2 (h2 @ pl_w2^T) + z epilogue ----
        // row 16m+8h+g has position 4g+2m+h -> kk = (4g+2m+h) & 15
        uint32_t fz[2][4][4];
#pragma unroll
        for (int j = 0; j < 8; ++j) {
            const char* q1 = smc + OFF_P1 + (8*j + g)*160 + T*8;
            const char* q2 = smc + OFF_P2 + (8*j + g)*160 + T*8;
            float c1[2][4] = {{0,0,0,0},{0,0,0,0}};
            float c2[2][4] = {{0,0,0,0},{0,0,0,0}};
#pragma unroll
            for (int t = 0; t < 4; ++t) {
                const uint2 v1 = *(const uint2*)(q1 + t*32);
                const uint2 v2 = *(const uint2*)(q2 + t*32);
                mma16816(c1[0], fa[0][t], v1.x, v1.y);
                mma16816(c1[1], fa[1][t], v1.x, v1.y);
                mma16816(c2[0], fb[0][t], v2.x, v2.y);
                mma16816(c2[1], fb[1][t], v2.x, v2.y);
            }
            const int cA = 8*j + 2*T;
            const float2 o1 = *(const float2*)(b1v + cA);
            const float2 o2 = *(const float2*)(b2v + cA);
#pragma unroll
            for (int m = 0; m < 2; ++m) {
                const int kk0 = (4*g + 2*m)     & 15;   // h = 0 (regs 0,1)
                const int kk1 = (4*g + 2*m + 1) & 15;   // h = 1 (regs 2,3)
                const float2 d0 = *(const float2*)(DDT + kk0*DPITCH + cA);
                const float2 d1 = *(const float2*)(DDT + kk1*DPITCH + cA);
                float z0 = (c1[m][0] + o1.x) + d0.x*(c2[m][0] + o2.x);
                float z1 = (c1[m][1] + o1.y) + d0.y*(c2[m][1] + o2.y);
                float z2 = (c1[m][2] + o1.x) + d1.x*(c2[m][2] + o2.x);
                float z3 = (c1[m][3] + o1.y) + d1.y*(c2[m][3] + o2.y);
                fz[m][j>>1][2*(j&1) + 0] = pack2(z0, z1);
                fz[m][j>>1][2*(j&1) + 1] = pack2(z2, z3);
            }
        }

        // ---- GEMM3 (z @ folded_ge_w1^T), relu -> h3 frags (reuse fa) ----
#pragma unroll
        for (int j = 0; j < 8; ++j) {
            const char* q3 = smc + OFF_P3 + (8*j + g)*160 + T*8;
            float c3[2][4] = {{0,0,0,0},{0,0,0,0}};
#pragma unroll
            for (int t = 0; t < 4; ++t) {
                const uint2 v3 = *(const uint2*)(q3 + t*32);
                mma16816(c3[0], fz[0][t], v3.x, v3.y);
                mma16816(c3[1], fz[1][t], v3.x, v3.y);
            }
            const int cA = 8*j + 2*T;
            const float2 o3 = *(const float2*)(b3v + cA);
#pragma unroll
            for (int m = 0; m < 2; ++m) {
                float h0  = fmaxf(c3[m][0] + o3.x, 0.f);
                float h1  = fmaxf(c3[m][1] + o3.y, 0.f);
                float h2_ = fmaxf(c3[m][2] + o3.x, 0.f);
                float h3_ = fmaxf(c3[m][3] + o3.y, 0.f);
                fa[m][j>>1][2*(j&1) + 0] = pack2(h0, h1);
                fa[m][j>>1][2*(j&1) + 1] = pack2(h2_, h3_);
            }
        }

        // ---- GEMM4 (h3 @ ge_w2^T) + bias + coalesced float4 store ----
        // channel c: lane (g,T) holds positions 4g..4g+3 as
        //   {c4[0][e], c4[0][2+e], c4[1][e], c4[1][2+e]}  (e = c & 1)
        float* ob = out + (size_t)b * 64 * NNK + pgb0;
#pragma unroll
        for (int j = 0; j < 8; ++j) {
            const char* q4 = smc + OFF_P4 + (8*j + g)*160 + T*8;
            float c4[2][4] = {{0,0,0,0},{0,0,0,0}};
#pragma unroll
            for (int t = 0; t < 4; ++t) {
                const uint2 v4 = *(const uint2*)(q4 + t*32);
                mma16816(c4[0], fa[0][t], v4.x, v4.y);
                mma16816(c4[1], fa[1][t], v4.x, v4.y);
            }
            const int cA = 8*j + 2*T;
            const float2 o4 = *(const float2*)(bov + cA);
            {
                float4 v = make_float4(c4[0][0] + o4.x, c4[0][2] + o4.x,
                                       c4[1][0] + o4.x, c4[1][2] + o4.x);
                *(float4*)(ob + (size_t)cA * NNK + 4*g) = v;
            }
            {
                float4 v = make_float4(c4[0][1] + o4.y, c4[0][3] + o4.y,
                                       c4[1][1] + o4.y, c4[1][3] + o4.y);
                *(float4*)(ob + (size_t)(cA+1) * NNK + 4*g) = v;
            }
        }
    }
}

extern "C" void kernel_launch(void* const* d_in, const int* in_sizes, int n_in,
                              void* d_out, int out_size) {
    (void)in_sizes; (void)n_in; (void)out_size;

    cudaFuncSetAttribute(geo_hmma_kernel,
                         cudaFuncAttributeMaxDynamicSharedMemorySize, SMEM_BYTES);

    geo_hmma_kernel<<<GRID, TPB, SMEM_BYTES>>>(
        (const float*)d_in[0],  (const float*)d_in[1],  (const float*)d_in[2],
        (const float*)d_in[3],  (const float*)d_in[4],  (const float*)d_in[5],
        (const float*)d_in[6],  (const float*)d_in[7],  (const float*)d_in[8],
        (const float*)d_in[9],  (const float*)d_in[10],
        (const float*)d_in[11], (const float*)d_in[12], (const float*)d_in[13],
        (const float*)d_in[14], (const float*)d_in[15], (const float*)d_in[16],
        (const float*)d_in[17], (const float*)d_in[18],
        (const float*)d_in[19], (const float*)d_in[20], (const float*)d_in[21],
        (const float*)d_in[22], (const float*)d_in[23], (const float*)d_in[24],
        (const float*)d_in[25], (const float*)d_in[26],
        (float*)d_out);
}